// round 6
// baseline (speedup 1.0000x reference)
#include <cuda_runtime.h>

// Row-pair-packed D: g_Dpair[a*9+k] = (D[2a][k], D[2a+1][k]) as f32x2 in u64,
// a=0..4 (row 9 is zero padding), k=0..8.  out = sum_r u[r] * (D[r] . v)
__device__ unsigned long long g_Dpair[46];

__device__ __forceinline__ unsigned long long pack2(float lo, float hi) {
    unsigned long long r;
    asm("mov.b64 %0, {%1, %2};" : "=l"(r) : "f"(lo), "f"(hi));
    return r;
}
__device__ __forceinline__ unsigned long long mul2(unsigned long long a, unsigned long long b) {
    unsigned long long d;
    asm("mul.rn.f32x2 %0, %1, %2;" : "=l"(d) : "l"(a), "l"(b));
    return d;
}
__device__ __forceinline__ unsigned long long fma2(unsigned long long a, unsigned long long b,
                                                   unsigned long long c) {
    unsigned long long d;
    asm("fma.rn.f32x2 %0, %1, %2, %3;" : "=l"(d) : "l"(a), "l"(b), "l"(c));
    return d;
}

// ---------------------------------------------------------------------------
// Prologue: build U (16x16) by evolving all 16 basis columns, form
// A = Re(U^dag Z0 U), transform to the 9x9 full-angle bilinear form D,
// then pack row-pairs. Launch: <<<1, 128>>>.
// ---------------------------------------------------------------------------
__global__ void qnn_prologue(const float* __restrict__ w) {
    __shared__ float Sr[16][16];   // Sr[col][i] = Re(U[i][col])
    __shared__ float Si[16][16];
    __shared__ float sA[16][16];
    __shared__ float Gs[8][4];     // {ar, ai, br, bi} per (layer,wire)
    __shared__ float sD9[81];      // D row-major [9][9]

    const int tid = threadIdx.x;   // 0..127
    const int col = tid >> 3;
    const int p   = tid & 7;

    Sr[col][p]     = (p == col) ? 1.f : 0.f;
    Sr[col][p + 8] = ((p + 8) == col) ? 1.f : 0.f;
    Si[col][p]     = 0.f;
    Si[col][p + 8] = 0.f;

    if (tid < 8) {
        float sa, ca, sb, cb, sc, cc;
        __sincosf(0.5f * w[3 * tid + 0], &sa, &ca);
        __sincosf(0.5f * w[3 * tid + 1], &sb, &cb);
        __sincosf(0.5f * w[3 * tid + 2], &sc, &cc);
        const float cbca = cb * ca, sbsa = sb * sa, sbca = sb * ca, cbsa = cb * sa;
        Gs[tid][0] = cc * cbca + sc * sbsa;   // ar
        Gs[tid][1] = cc * sbsa - sc * cbca;   // ai
        Gs[tid][2] = cc * sbca + sc * cbsa;   // br
        Gs[tid][3] = sc * sbca - cc * cbsa;   // bi
    }
    __syncthreads();

    // wire q <-> bit (3-q)
    for (int g = 0; g < 8; ++g) {
        const int q = g & 3;
        const int stride = 8 >> q;
        const int i0 = ((p & ~(stride - 1)) << 1) | (p & (stride - 1));
        const int i1 = i0 + stride;
        const float ar = Gs[g][0], ai = Gs[g][1], br = Gs[g][2], bi = Gs[g][3];
        const float a0r = Sr[col][i0], a0i = Si[col][i0];
        const float a1r = Sr[col][i1], a1i = Si[col][i1];
        Sr[col][i0] = ar * a0r - ai * a0i - br * a1r - bi * a1i;
        Si[col][i0] = ar * a0i + ai * a0r - br * a1i + bi * a1r;
        Sr[col][i1] = br * a0r - bi * a0i + ar * a1r + ai * a1i;
        Si[col][i1] = br * a0i + bi * a0r + ar * a1i - ai * a1r;
        __syncthreads();

        if (q == 3) {
            const int cw[4] = {0, 1, 2, 3};
            const int tw[4] = {1, 2, 3, 0};
            for (int k = 0; k < 4; ++k) {
                const int bc = 3 - cw[k], bt = 3 - tw[k];
                if (p < 4) {
                    int o0 = -1, o1 = -1;
                    for (int b = 0; b < 4; ++b)
                        if (b != bc && b != bt) { if (o0 < 0) o0 = b; else o1 = b; }
                    const int i = (1 << bc) | ((p & 1) << o0) | (((p >> 1) & 1) << o1);
                    const int j = i | (1 << bt);
                    float tr = Sr[col][i], ti = Si[col][i];
                    Sr[col][i] = Sr[col][j];  Si[col][i] = Si[col][j];
                    Sr[col][j] = tr;          Si[col][j] = ti;
                }
                __syncthreads();
            }
        }
    }

    for (int e = tid; e < 256; e += 128) {
        const int j = e >> 4, l = e & 15;
        float acc = 0.f;
        for (int i = 0; i < 16; ++i) {
            const float sgn = (i < 8) ? 1.f : -1.f;
            acc += sgn * (Sr[j][i] * Sr[l][i] + Si[j][i] * Si[l][i]);
        }
        sA[j][l] = acc;
    }
    __syncthreads();

    // Half-angle product basis -> full-angle (1,cos,sin) basis, rows a, cols b.
    if (tid < 81) {
        const int a = tid / 9, b = tid % 9;
        const int t[4] = { a / 3, a % 3, b / 3, b % 3 };
        float d = 0.f;
        for (int k = 0; k < 16; ++k) {
            int j = 0, l = 0;
            float sgn = 1.f;
            for (int qq = 0; qq < 4; ++qq) {
                const int kk = (k >> qq) & 1;
                int jq, lq;
                if (t[qq] == 2) { jq = kk; lq = 1 - kk; }
                else            { jq = kk; lq = kk; if (t[qq] == 1 && kk) sgn = -sgn; }
                j |= jq << (3 - qq);
                l |= lq << (3 - qq);
            }
            d += sgn * sA[j][l];
        }
        sD9[tid] = d * 0.0625f;
    }
    __syncthreads();

    // Pack row pairs: (row 2a, row 2a+1), row 9 = zeros.
    if (tid < 45) {
        const int a = tid / 9, k = tid % 9;
        const float lo = sD9[(2 * a) * 9 + k];
        const float hi = (2 * a + 1 < 9) ? sD9[(2 * a + 1) * 9 + k] : 0.f;
        g_Dpair[tid] = pack2(lo, hi);
    }
}

// ---------------------------------------------------------------------------
// Main: persistent grid-stride, ONE sample per iteration. D lives in registers
// (45 packed row-pairs loaded once). f32x2 lanes carry two D-rows of the same
// sample; no shared/constant traffic in the loop.
// ---------------------------------------------------------------------------
__global__ void __launch_bounds__(128) qnn_main(const float4* __restrict__ x4,
                                                float* __restrict__ out, int n) {
    // one-time: load D row-pairs into registers
    unsigned long long P[45];
#pragma unroll
    for (int k = 0; k < 45; ++k) P[k] = g_Dpair[k];

    int i = blockIdx.x * blockDim.x + threadIdx.x;
    const int stride = gridDim.x * blockDim.x;
    if (i >= n) return;

    float4 cur = x4[i];

    for (;;) {
        const int nx = i + stride;
        const bool have = nx < n;
        float4 nxt;
        if (have) nxt = x4[nx];

        float c0, s0, c1, s1, c2, s2, c3, s3;
        __sincosf(cur.x, &s0, &c0);
        __sincosf(cur.y, &s1, &c1);
        __sincosf(cur.z, &s2, &c2);
        __sincosf(cur.w, &s3, &c3);

        // v duplicated across both lanes: v = {1,c3,s3,c2,c2c3,c2s3,s2,s2c3,s2s3}
        const unsigned long long pv1 = pack2(c3, c3);
        const unsigned long long pv2 = pack2(s3, s3);
        const unsigned long long pv3 = pack2(c2, c2);
        const unsigned long long pv6 = pack2(s2, s2);
        const unsigned long long pv4 = mul2(pv3, pv1);
        const unsigned long long pv5 = mul2(pv3, pv2);
        const unsigned long long pv7 = mul2(pv6, pv1);
        const unsigned long long pv8 = mul2(pv6, pv2);

        // 5 independent row-pair dots (v[0]=1 -> P[..0] is the init term)
        unsigned long long d0, d1, d2, d3, d4;
#define PAIR_DOT(dst, a)                                          \
        {                                                         \
            unsigned long long t = P[(a) * 9 + 0];                \
            t = fma2(P[(a) * 9 + 1], pv1, t);                     \
            t = fma2(P[(a) * 9 + 2], pv2, t);                     \
            t = fma2(P[(a) * 9 + 3], pv3, t);                     \
            t = fma2(P[(a) * 9 + 4], pv4, t);                     \
            t = fma2(P[(a) * 9 + 5], pv5, t);                     \
            t = fma2(P[(a) * 9 + 6], pv6, t);                     \
            t = fma2(P[(a) * 9 + 7], pv7, t);                     \
            t = fma2(P[(a) * 9 + 8], pv8, t);                     \
            dst = t;                                              \
        }
        PAIR_DOT(d0, 0);
        PAIR_DOT(d1, 1);
        PAIR_DOT(d2, 2);
        PAIR_DOT(d3, 3);
        PAIR_DOT(d4, 4);
#undef PAIR_DOT

        // u pairs: (1,c1) (s1,c0) (c0c1,c0s1) (s0,s0c1) (s0s1,0)
        const unsigned long long pu0 = pack2(1.f, c1);
        const unsigned long long pu1 = pack2(s1, c0);
        const unsigned long long pc0d = pack2(c0, c0);
        const unsigned long long ps0d = pack2(s0, s0);
        const unsigned long long pu2 = mul2(pc0d, pack2(c1, s1));
        const unsigned long long pu3 = mul2(ps0d, pu0);
        const unsigned long long pu4 = mul2(ps0d, pack2(s1, 0.f));

        unsigned long long acc = mul2(pu0, d0);
        acc = fma2(pu1, d1, acc);
        acc = fma2(pu2, d2, acc);
        acc = fma2(pu3, d3, acc);
        acc = fma2(pu4, d4, acc);

        float lo, hi;
        asm("mov.b64 {%0, %1}, %2;" : "=f"(lo), "=f"(hi) : "l"(acc));
        out[i] = lo + hi;

        if (!have) break;
        cur = nxt;
        i = nx;
    }
}

extern "C" void kernel_launch(void* const* d_in, const int* in_sizes, int n_in,
                              void* d_out, int out_size) {
    const float* x = (const float*)d_in[0];
    const float* w = (const float*)d_in[1];
    float* out = (float*)d_out;
    const int B = out_size;

    qnn_prologue<<<1, 128>>>(w);

    int blocks = 148 * 4;                 // persistent; reg-limited residency
    const int maxb = (B + 127) / 128;
    if (blocks > maxb) blocks = maxb;
    qnn_main<<<blocks, 128>>>((const float4*)x, out, B);
}

// round 7
// speedup vs baseline: 1.0191x; 1.0191x over previous
#include <cuda_runtime.h>

// Row-pair-packed D: g_Dpair[a*9+k] = (D[2a][k], D[2a+1][k]) as f32x2 in u64,
// a=0..4 (row 9 is zero padding), k=0..8.  out = sum_r u[r] * (D[r] . v)
__device__ unsigned long long g_Dpair[45];

__device__ __forceinline__ unsigned long long pack2(float lo, float hi) {
    unsigned long long r;
    asm("mov.b64 %0, {%1, %2};" : "=l"(r) : "f"(lo), "f"(hi));
    return r;
}
__device__ __forceinline__ unsigned long long mul2(unsigned long long a, unsigned long long b) {
    unsigned long long d;
    asm("mul.rn.f32x2 %0, %1, %2;" : "=l"(d) : "l"(a), "l"(b));
    return d;
}
__device__ __forceinline__ unsigned long long fma2(unsigned long long a, unsigned long long b,
                                                   unsigned long long c) {
    unsigned long long d;
    asm("fma.rn.f32x2 %0, %1, %2, %3;" : "=l"(d) : "l"(a), "l"(b), "l"(c));
    return d;
}

// ---------------------------------------------------------------------------
// Prologue: build U (16x16) by evolving all 16 basis columns, form
// A = Re(U^dag Z0 U), transform to the 9x9 full-angle bilinear form D,
// then pack row-pairs. Launch: <<<1, 128>>>.
// ---------------------------------------------------------------------------
__global__ void qnn_prologue(const float* __restrict__ w) {
    __shared__ float Sr[16][16];   // Sr[col][i] = Re(U[i][col])
    __shared__ float Si[16][16];
    __shared__ float sA[16][16];
    __shared__ float Gs[8][4];     // {ar, ai, br, bi} per (layer,wire)
    __shared__ float sD9[81];      // D row-major [9][9]

    const int tid = threadIdx.x;   // 0..127
    const int col = tid >> 3;
    const int p   = tid & 7;

    Sr[col][p]     = (p == col) ? 1.f : 0.f;
    Sr[col][p + 8] = ((p + 8) == col) ? 1.f : 0.f;
    Si[col][p]     = 0.f;
    Si[col][p + 8] = 0.f;

    if (tid < 8) {
        float sa, ca, sb, cb, sc, cc;
        __sincosf(0.5f * w[3 * tid + 0], &sa, &ca);
        __sincosf(0.5f * w[3 * tid + 1], &sb, &cb);
        __sincosf(0.5f * w[3 * tid + 2], &sc, &cc);
        const float cbca = cb * ca, sbsa = sb * sa, sbca = sb * ca, cbsa = cb * sa;
        Gs[tid][0] = cc * cbca + sc * sbsa;   // ar
        Gs[tid][1] = cc * sbsa - sc * cbca;   // ai
        Gs[tid][2] = cc * sbca + sc * cbsa;   // br
        Gs[tid][3] = sc * sbca - cc * cbsa;   // bi
    }
    __syncthreads();

    // wire q <-> bit (3-q)
    for (int g = 0; g < 8; ++g) {
        const int q = g & 3;
        const int stride = 8 >> q;
        const int i0 = ((p & ~(stride - 1)) << 1) | (p & (stride - 1));
        const int i1 = i0 + stride;
        const float ar = Gs[g][0], ai = Gs[g][1], br = Gs[g][2], bi = Gs[g][3];
        const float a0r = Sr[col][i0], a0i = Si[col][i0];
        const float a1r = Sr[col][i1], a1i = Si[col][i1];
        Sr[col][i0] = ar * a0r - ai * a0i - br * a1r - bi * a1i;
        Si[col][i0] = ar * a0i + ai * a0r - br * a1i + bi * a1r;
        Sr[col][i1] = br * a0r - bi * a0i + ar * a1r + ai * a1i;
        Si[col][i1] = br * a0i + bi * a0r + ar * a1i - ai * a1r;
        __syncthreads();

        if (q == 3) {
            const int cw[4] = {0, 1, 2, 3};
            const int tw[4] = {1, 2, 3, 0};
            for (int k = 0; k < 4; ++k) {
                const int bc = 3 - cw[k], bt = 3 - tw[k];
                if (p < 4) {
                    int o0 = -1, o1 = -1;
                    for (int b = 0; b < 4; ++b)
                        if (b != bc && b != bt) { if (o0 < 0) o0 = b; else o1 = b; }
                    const int i = (1 << bc) | ((p & 1) << o0) | (((p >> 1) & 1) << o1);
                    const int j = i | (1 << bt);
                    float tr = Sr[col][i], ti = Si[col][i];
                    Sr[col][i] = Sr[col][j];  Si[col][i] = Si[col][j];
                    Sr[col][j] = tr;          Si[col][j] = ti;
                }
                __syncthreads();
            }
        }
    }

    for (int e = tid; e < 256; e += 128) {
        const int j = e >> 4, l = e & 15;
        float acc = 0.f;
        for (int i = 0; i < 16; ++i) {
            const float sgn = (i < 8) ? 1.f : -1.f;
            acc += sgn * (Sr[j][i] * Sr[l][i] + Si[j][i] * Si[l][i]);
        }
        sA[j][l] = acc;
    }
    __syncthreads();

    // Half-angle product basis -> full-angle (1,cos,sin) basis, rows a, cols b.
    if (tid < 81) {
        const int a = tid / 9, b = tid % 9;
        const int t[4] = { a / 3, a % 3, b / 3, b % 3 };
        float d = 0.f;
        for (int k = 0; k < 16; ++k) {
            int j = 0, l = 0;
            float sgn = 1.f;
            for (int qq = 0; qq < 4; ++qq) {
                const int kk = (k >> qq) & 1;
                int jq, lq;
                if (t[qq] == 2) { jq = kk; lq = 1 - kk; }
                else            { jq = kk; lq = kk; if (t[qq] == 1 && kk) sgn = -sgn; }
                j |= jq << (3 - qq);
                l |= lq << (3 - qq);
            }
            d += sgn * sA[j][l];
        }
        sD9[tid] = d * 0.0625f;
    }
    __syncthreads();

    // Pack row pairs: (row 2a, row 2a+1), row 9 = zeros.
    if (tid < 45) {
        const int a = tid / 9, k = tid % 9;
        const float lo = sD9[(2 * a) * 9 + k];
        const float hi = (2 * a + 1 < 9) ? sD9[(2 * a + 1) * 9 + k] : 0.f;
        g_Dpair[tid] = pack2(lo, hi);
    }
}

// ---------------------------------------------------------------------------
// Main: persistent grid-stride, ONE sample per iteration, 2-deep input
// prefetch. D lives entirely in registers (45 packed row-pairs, loaded once;
// launch_bounds(128,3) leaves a 168-register budget so nothing spills).
// f32x2 lanes carry two D-rows of the same sample.
// ---------------------------------------------------------------------------
__global__ void __launch_bounds__(128, 3) qnn_main(const float4* __restrict__ x4,
                                                   float* __restrict__ out, int n) {
    // one-time: load D row-pairs into registers
    unsigned long long P[45];
#pragma unroll
    for (int k = 0; k < 45; ++k) P[k] = g_Dpair[k];

    const int stride = gridDim.x * blockDim.x;
    int i0 = blockIdx.x * blockDim.x + threadIdx.x;
    if (i0 >= n) return;

    int i1 = i0 + stride;
    int i2 = i1 + stride;
    float4 f0 = x4[i0];
    float4 f1, f2;
    if (i1 < n) f1 = x4[i1];

    while (true) {
        if (i2 < n) f2 = x4[i2];

        float c0, s0, c1, s1, c2, s2, c3, s3;
        __sincosf(f0.x, &s0, &c0);
        __sincosf(f0.y, &s1, &c1);
        __sincosf(f0.z, &s2, &c2);
        __sincosf(f0.w, &s3, &c3);

        // v duplicated across both lanes: v = {1,c3,s3,c2,c2c3,c2s3,s2,s2c3,s2s3}
        const unsigned long long pv1 = pack2(c3, c3);
        const unsigned long long pv2 = pack2(s3, s3);
        const unsigned long long pv3 = pack2(c2, c2);
        const unsigned long long pv6 = pack2(s2, s2);
        const unsigned long long pv4 = mul2(pv3, pv1);
        const unsigned long long pv5 = mul2(pv3, pv2);
        const unsigned long long pv7 = mul2(pv6, pv1);
        const unsigned long long pv8 = mul2(pv6, pv2);

        // 5 independent row-pair dots (v[0]=1 -> P[..0] is the init term)
        unsigned long long d0, d1, d2, d3, d4;
#define PAIR_DOT(dst, a)                                          \
        {                                                         \
            unsigned long long t = P[(a) * 9 + 0];                \
            t = fma2(P[(a) * 9 + 1], pv1, t);                     \
            t = fma2(P[(a) * 9 + 2], pv2, t);                     \
            t = fma2(P[(a) * 9 + 3], pv3, t);                     \
            t = fma2(P[(a) * 9 + 4], pv4, t);                     \
            t = fma2(P[(a) * 9 + 5], pv5, t);                     \
            t = fma2(P[(a) * 9 + 6], pv6, t);                     \
            t = fma2(P[(a) * 9 + 7], pv7, t);                     \
            t = fma2(P[(a) * 9 + 8], pv8, t);                     \
            dst = t;                                              \
        }
        PAIR_DOT(d0, 0);
        PAIR_DOT(d1, 1);
        PAIR_DOT(d2, 2);
        PAIR_DOT(d3, 3);
        PAIR_DOT(d4, 4);
#undef PAIR_DOT

        // u pairs: (1,c1) (s1,c0) (c0c1,c0s1) (s0,s0c1) (s0s1,0)
        const unsigned long long pu0 = pack2(1.f, c1);
        const unsigned long long pu1 = pack2(s1, c0);
        const unsigned long long pc0d = pack2(c0, c0);
        const unsigned long long ps0d = pack2(s0, s0);
        const unsigned long long pu2 = mul2(pc0d, pack2(c1, s1));
        const unsigned long long pu3 = mul2(ps0d, pu0);
        const unsigned long long pu4 = mul2(ps0d, pack2(s1, 0.f));

        unsigned long long acc = mul2(pu0, d0);
        acc = fma2(pu1, d1, acc);
        acc = fma2(pu2, d2, acc);
        acc = fma2(pu3, d3, acc);
        acc = fma2(pu4, d4, acc);

        float lo, hi;
        asm("mov.b64 {%0, %1}, %2;" : "=f"(lo), "=f"(hi) : "l"(acc));
        out[i0] = lo + hi;

        if (i1 >= n) break;
        f0 = f1;  f1 = f2;
        i0 = i1;  i1 = i2;  i2 = i2 + stride;
    }
}

extern "C" void kernel_launch(void* const* d_in, const int* in_sizes, int n_in,
                              void* d_out, int out_size) {
    const float* x = (const float*)d_in[0];
    const float* w = (const float*)d_in[1];
    float* out = (float*)d_out;
    const int B = out_size;

    qnn_prologue<<<1, 128>>>(w);

    int blocks = 148 * 3;                 // persistent: 3 CTAs/SM (reg budget 168)
    const int maxb = (B + 127) / 128;
    if (blocks > maxb) blocks = maxb;
    qnn_main<<<blocks, 128>>>((const float4*)x, out, B);
}

// round 8
// speedup vs baseline: 1.1798x; 1.1576x over previous
#include <cuda_runtime.h>

// Packed D matrix in constant memory: out = u^T D v; each element duplicated
// as (d,d) in a 64-bit word for fma.rn.f32x2. Rows padded to 10 u64 (80B).
// Written by the prologue kernel through the symbol's global-memory aperture
// (D is identical on every launch, so cross-launch const-cache reuse is benign).
__constant__ __align__(16) unsigned long long cDp[90];

__device__ __forceinline__ unsigned long long pack2(float lo, float hi) {
    unsigned long long r;
    asm("mov.b64 %0, {%1, %2};" : "=l"(r) : "f"(lo), "f"(hi));
    return r;
}
__device__ __forceinline__ unsigned long long mul2(unsigned long long a, unsigned long long b) {
    unsigned long long d;
    asm("mul.rn.f32x2 %0, %1, %2;" : "=l"(d) : "l"(a), "l"(b));
    return d;
}
__device__ __forceinline__ unsigned long long fma2(unsigned long long a, unsigned long long b,
                                                   unsigned long long c) {
    unsigned long long d;
    asm("fma.rn.f32x2 %0, %1, %2, %3;" : "=l"(d) : "l"(a), "l"(b), "l"(c));
    return d;
}

// ---------------------------------------------------------------------------
// Prologue: build U (16x16) by evolving all 16 basis columns, form
// A = Re(U^dag Z0 U), transform to the 9x9 full-angle bilinear form D, pack,
// and store straight into the constant bank via dDp (global aperture).
// Fused gate G = RZ(c)RY(b)RX(a) = [[alpha, -conj(beta)],[beta, conj(alpha)]].
// Launch: <<<1, 128>>>.
// ---------------------------------------------------------------------------
__global__ void qnn_prologue(const float* __restrict__ w,
                             unsigned long long* __restrict__ dDp) {
    __shared__ float Sr[16][16];   // Sr[col][i] = Re(U[i][col])
    __shared__ float Si[16][16];
    __shared__ float sA[16][16];
    __shared__ float Gs[8][4];     // {ar, ai, br, bi} per (layer,wire)

    const int tid = threadIdx.x;   // 0..127
    const int col = tid >> 3;
    const int p   = tid & 7;

    Sr[col][p]     = (p == col) ? 1.f : 0.f;
    Sr[col][p + 8] = ((p + 8) == col) ? 1.f : 0.f;
    Si[col][p]     = 0.f;
    Si[col][p + 8] = 0.f;

    if (tid < 8) {
        float sa, ca, sb, cb, sc, cc;
        __sincosf(0.5f * w[3 * tid + 0], &sa, &ca);
        __sincosf(0.5f * w[3 * tid + 1], &sb, &cb);
        __sincosf(0.5f * w[3 * tid + 2], &sc, &cc);
        const float cbca = cb * ca, sbsa = sb * sa, sbca = sb * ca, cbsa = cb * sa;
        Gs[tid][0] = cc * cbca + sc * sbsa;   // ar
        Gs[tid][1] = cc * sbsa - sc * cbca;   // ai
        Gs[tid][2] = cc * sbca + sc * cbsa;   // br
        Gs[tid][3] = sc * sbca - cc * cbsa;   // bi
    }
    __syncthreads();

    // wire q <-> bit (3-q)
    for (int g = 0; g < 8; ++g) {
        const int q = g & 3;
        const int stride = 8 >> q;
        const int i0 = ((p & ~(stride - 1)) << 1) | (p & (stride - 1));
        const int i1 = i0 + stride;
        const float ar = Gs[g][0], ai = Gs[g][1], br = Gs[g][2], bi = Gs[g][3];
        const float a0r = Sr[col][i0], a0i = Si[col][i0];
        const float a1r = Sr[col][i1], a1i = Si[col][i1];
        Sr[col][i0] = ar * a0r - ai * a0i - br * a1r - bi * a1i;
        Si[col][i0] = ar * a0i + ai * a0r - br * a1i + bi * a1r;
        Sr[col][i1] = br * a0r - bi * a0i + ar * a1r + ai * a1i;
        Si[col][i1] = br * a0i + bi * a0r + ar * a1i - ai * a1r;
        __syncthreads();

        if (q == 3) {
            const int cw[4] = {0, 1, 2, 3};
            const int tw[4] = {1, 2, 3, 0};
            for (int k = 0; k < 4; ++k) {
                const int bc = 3 - cw[k], bt = 3 - tw[k];
                if (p < 4) {
                    int o0 = -1, o1 = -1;
                    for (int b = 0; b < 4; ++b)
                        if (b != bc && b != bt) { if (o0 < 0) o0 = b; else o1 = b; }
                    const int i = (1 << bc) | ((p & 1) << o0) | (((p >> 1) & 1) << o1);
                    const int j = i | (1 << bt);
                    float tr = Sr[col][i], ti = Si[col][i];
                    Sr[col][i] = Sr[col][j];  Si[col][i] = Si[col][j];
                    Sr[col][j] = tr;          Si[col][j] = ti;
                }
                __syncthreads();
            }
        }
    }

    for (int e = tid; e < 256; e += 128) {
        const int j = e >> 4, l = e & 15;
        float acc = 0.f;
        for (int i = 0; i < 16; ++i) {
            const float sgn = (i < 8) ? 1.f : -1.f;
            acc += sgn * (Sr[j][i] * Sr[l][i] + Si[j][i] * Si[l][i]);
        }
        sA[j][l] = acc;
    }
    __syncthreads();

    // Half-angle product basis -> full-angle (1,cos,sin) basis; pack (d,d).
    if (tid < 90) {
        const int a = tid / 10, b = tid % 10;
        float d = 0.f;
        if (b < 9) {
            const int t[4] = { a / 3, a % 3, b / 3, b % 3 };
            for (int k = 0; k < 16; ++k) {
                int j = 0, l = 0;
                float sgn = 1.f;
                for (int qq = 0; qq < 4; ++qq) {
                    const int kk = (k >> qq) & 1;
                    int jq, lq;
                    if (t[qq] == 2) { jq = kk; lq = 1 - kk; }
                    else            { jq = kk; lq = kk; if (t[qq] == 1 && kk) sgn = -sgn; }
                    j |= jq << (3 - qq);
                    l |= lq << (3 - qq);
                }
                d += sgn * sA[j][l];
            }
            d *= 0.0625f;
        }
        dDp[tid] = pack2(d, d);
        __threadfence();
    }
}

// ---------------------------------------------------------------------------
// Main: two samples per thread (one f32x2 stream), D from the constant bank.
// This is the measured-fastest main-loop configuration (R2 body).
// ---------------------------------------------------------------------------
__global__ void __launch_bounds__(256) qnn_main(const float4* __restrict__ x4,
                                               float2* __restrict__ out, int npairs) {
    const int idx = blockIdx.x * blockDim.x + threadIdx.x;
    if (idx >= npairs) return;

    const float4 xa = x4[2 * idx];
    const float4 xb = x4[2 * idx + 1];

    float c0a, s0a, c1a, s1a, c2a, s2a, c3a, s3a;
    float c0b, s0b, c1b, s1b, c2b, s2b, c3b, s3b;
    __sincosf(xa.x, &s0a, &c0a);  __sincosf(xa.y, &s1a, &c1a);
    __sincosf(xa.z, &s2a, &c2a);  __sincosf(xa.w, &s3a, &c3a);
    __sincosf(xb.x, &s0b, &c0b);  __sincosf(xb.y, &s1b, &c1b);
    __sincosf(xb.z, &s2b, &c2b);  __sincosf(xb.w, &s3b, &c3b);

    const unsigned long long pc0 = pack2(c0a, c0b), ps0 = pack2(s0a, s0b);
    const unsigned long long pc1 = pack2(c1a, c1b), ps1 = pack2(s1a, s1b);
    const unsigned long long pc2 = pack2(c2a, c2b), ps2 = pack2(s2a, s2b);
    const unsigned long long pc3 = pack2(c3a, c3b), ps3 = pack2(s3a, s3b);

    // v[0]=1 implicit; v[1..8] = {c3, s3, c2, c2c3, c2s3, s2, s2c3, s2s3}
    unsigned long long pv[9];
    pv[1] = pc3;             pv[2] = ps3;
    pv[3] = pc2;             pv[4] = mul2(pc2, pc3);
    pv[5] = mul2(pc2, ps3);  pv[6] = ps2;
    pv[7] = mul2(ps2, pc3);  pv[8] = mul2(ps2, ps3);
    // u[0]=1 implicit; u[1..8] = {c1, s1, c0, c0c1, c0s1, s0, s0c1, s0s1}
    unsigned long long pu[9];
    pu[1] = pc1;             pu[2] = ps1;
    pu[3] = pc0;             pu[4] = mul2(pc0, pc1);
    pu[5] = mul2(pc0, ps1);  pu[6] = ps0;
    pu[7] = mul2(ps0, pc1);  pu[8] = mul2(ps0, ps1);

    unsigned long long acc = 0;
#pragma unroll
    for (int a = 0; a < 9; ++a) {
        const ulonglong2* row = reinterpret_cast<const ulonglong2*>(cDp + a * 10);
        const ulonglong2 r0 = row[0], r1 = row[1], r2 = row[2], r3 = row[3];
        const unsigned long long d8 = cDp[a * 10 + 8];
        unsigned long long dot = r0.x;                 // * v[0] == 1
        dot = fma2(r0.y, pv[1], dot);
        dot = fma2(r1.x, pv[2], dot);
        dot = fma2(r1.y, pv[3], dot);
        dot = fma2(r2.x, pv[4], dot);
        dot = fma2(r2.y, pv[5], dot);
        dot = fma2(r3.x, pv[6], dot);
        dot = fma2(r3.y, pv[7], dot);
        dot = fma2(d8,   pv[8], dot);
        if (a == 0) acc = dot;                          // * u[0] == 1
        else        acc = fma2(pu[a], dot, acc);
    }

    float lo, hi;
    asm("mov.b64 {%0, %1}, %2;" : "=f"(lo), "=f"(hi) : "l"(acc));
    out[idx] = make_float2(lo, hi);
}

extern "C" void kernel_launch(void* const* d_in, const int* in_sizes, int n_in,
                              void* d_out, int out_size) {
    const float* x = (const float*)d_in[0];
    const float* w = (const float*)d_in[1];
    float2* out = (float2*)d_out;
    const int B = out_size;
    const int npairs = B >> 1;

    void* dDp = nullptr;
    cudaGetSymbolAddress(&dDp, cDp);

    qnn_prologue<<<1, 128>>>(w, (unsigned long long*)dDp);

    const int blocks = (npairs + 255) / 256;
    qnn_main<<<blocks, 256>>>((const float4*)x, out, npairs);
}

// round 9
// speedup vs baseline: 1.1975x; 1.0150x over previous
#include <cuda_runtime.h>

// Packed D matrix in constant memory: out = u^T D v; each element duplicated
// as (d,d) in a 64-bit word for fma.rn.f32x2. Rows padded to 10 u64 (80B).
// Written by the prologue kernel through the symbol's global-memory aperture.
__constant__ __align__(16) unsigned long long cDp[90];

__device__ __forceinline__ unsigned long long pack2(float lo, float hi) {
    unsigned long long r;
    asm("mov.b64 %0, {%1, %2};" : "=l"(r) : "f"(lo), "f"(hi));
    return r;
}
__device__ __forceinline__ unsigned long long mul2(unsigned long long a, unsigned long long b) {
    unsigned long long d;
    asm("mul.rn.f32x2 %0, %1, %2;" : "=l"(d) : "l"(a), "l"(b));
    return d;
}
__device__ __forceinline__ unsigned long long fma2(unsigned long long a, unsigned long long b,
                                                   unsigned long long c) {
    unsigned long long d;
    asm("fma.rn.f32x2 %0, %1, %2, %3;" : "=l"(d) : "l"(a), "l"(b), "l"(c));
    return d;
}

// ---------------------------------------------------------------------------
// Prologue: build U (16x16) by evolving all 16 basis columns (gate sync is
// warp-local: each column's 16 amplitudes belong to 8 threads of one warp),
// form A = Re(U^dag Z0 U), then apply the half-angle->full-angle basis change
// as 4 staged single-wire contractions (256->192->144->108->81), pack, and
// store into the constant bank via dDp. Launch: <<<1, 128>>>.
// ---------------------------------------------------------------------------
__global__ void qnn_prologue(const float* __restrict__ w,
                             unsigned long long* __restrict__ dDp) {
    __shared__ float Sr[16][16];   // Sr[col][i] = Re(U[i][col])
    __shared__ float Si[16][16];
    __shared__ float Gs[8][4];     // {ar, ai, br, bi} per (layer,wire)
    __shared__ float Ta[256];      // stage ping
    __shared__ float Tb[256];      // stage pong

    const int tid = threadIdx.x;   // 0..127
    const int col = tid >> 3;
    const int p   = tid & 7;

    Sr[col][p]     = (p == col) ? 1.f : 0.f;
    Sr[col][p + 8] = ((p + 8) == col) ? 1.f : 0.f;
    Si[col][p]     = 0.f;
    Si[col][p + 8] = 0.f;

    if (tid < 8) {
        float sa, ca, sb, cb, sc, cc;
        __sincosf(0.5f * w[3 * tid + 0], &sa, &ca);
        __sincosf(0.5f * w[3 * tid + 1], &sb, &cb);
        __sincosf(0.5f * w[3 * tid + 2], &sc, &cc);
        const float cbca = cb * ca, sbsa = sb * sa, sbca = sb * ca, cbsa = cb * sa;
        Gs[tid][0] = cc * cbca + sc * sbsa;   // ar
        Gs[tid][1] = cc * sbsa - sc * cbca;   // ai
        Gs[tid][2] = cc * sbca + sc * cbsa;   // br
        Gs[tid][3] = sc * sbca - cc * cbsa;   // bi
    }
    __syncthreads();

    // Gate evolution. wire q <-> bit (3-q). All ops on column `col` involve
    // only its 8 owner threads (same warp) -> __syncwarp suffices.
    for (int g = 0; g < 8; ++g) {
        const int q = g & 3;
        const int stride = 8 >> q;
        const int i0 = ((p & ~(stride - 1)) << 1) | (p & (stride - 1));
        const int i1 = i0 + stride;
        const float ar = Gs[g][0], ai = Gs[g][1], br = Gs[g][2], bi = Gs[g][3];
        const float a0r = Sr[col][i0], a0i = Si[col][i0];
        const float a1r = Sr[col][i1], a1i = Si[col][i1];
        Sr[col][i0] = ar * a0r - ai * a0i - br * a1r - bi * a1i;
        Si[col][i0] = ar * a0i + ai * a0r - br * a1i + bi * a1r;
        Sr[col][i1] = br * a0r - bi * a0i + ar * a1r + ai * a1i;
        Si[col][i1] = br * a0i + bi * a0r + ar * a1i - ai * a1r;
        __syncwarp();

        if (q == 3) {
            // CNOT ring: (0->1),(1->2),(2->3),(3->0)
            const int cw[4] = {0, 1, 2, 3};
            const int tw[4] = {1, 2, 3, 0};
            for (int k = 0; k < 4; ++k) {
                const int bc = 3 - cw[k], bt = 3 - tw[k];
                if (p < 4) {
                    int o0 = -1, o1 = -1;
                    for (int b = 0; b < 4; ++b)
                        if (b != bc && b != bt) { if (o0 < 0) o0 = b; else o1 = b; }
                    const int i = (1 << bc) | ((p & 1) << o0) | (((p >> 1) & 1) << o1);
                    const int j = i | (1 << bt);
                    float tr = Sr[col][i], ti = Si[col][i];
                    Sr[col][i] = Sr[col][j];  Si[col][i] = Si[col][j];
                    Sr[col][j] = tr;          Si[col][j] = ti;
                }
                __syncwarp();
            }
        }
    }
    __syncthreads();

    // A[j][l] = sum_i sgn_i * Re(conj(U[i][j]) U[i][l]), sgn=+1 (i<8), -1 (i>=8)
    for (int e = tid; e < 256; e += 128) {
        const int j = e >> 4, l = e & 15;
        float acc = 0.f;
        for (int i = 0; i < 16; ++i) {
            const float sgn = (i < 8) ? 1.f : -1.f;
            acc += sgn * (Sr[j][i] * Sr[l][i] + Si[j][i] * Si[l][i]);
        }
        Ta[j * 16 + l] = acc;      // stage-0 input: [1][16][16]
    }
    __syncthreads();

    // 4 staged contractions, one per wire. Stage s input shape
    // [3^s][H][H] with H=2^(4-s), linear idx = (m*H + rj)*H + rl.
    // Output: t in {0,1,2} replaces the wire-s (j,l) bit pair:
    //   t=0: (A00+A11)/2,  t=1: (A00-A11)/2,  t=2: (A01+A10)/2
    {
        float* cur = Ta;
        float* nxt = Tb;
        int M = 1;
#pragma unroll
        for (int s = 0; s < 4; ++s) {
            const int Hi = 1 << (4 - s);
            const int Ho = Hi >> 1;
            const int Nout = M * 3 * Ho * Ho;
            for (int e = tid; e < Nout; e += 128) {
                int r = e;
                const int rl = r % Ho;  r /= Ho;
                const int rj = r % Ho;  r /= Ho;
                const int t  = r % 3;   const int m = r / 3;
                const float a00 = cur[(m * Hi + rj) * Hi + rl];
                const float a11 = cur[(m * Hi + Ho + rj) * Hi + Ho + rl];
                const float a01 = cur[(m * Hi + rj) * Hi + Ho + rl];
                const float a10 = cur[(m * Hi + Ho + rj) * Hi + rl];
                float v;
                if (t == 0)      v = a00 + a11;
                else if (t == 1) v = a00 - a11;
                else             v = a01 + a10;
                nxt[e] = 0.5f * v;
            }
            __syncthreads();
            float* tmp = cur; cur = nxt; nxt = tmp;
            M *= 3;
        }
        // Final D[a*9+b] lives in `cur` (= Ta after 4 swaps). Pack (d,d).
        if (tid < 90) {
            const int a = tid / 10, b = tid % 10;
            const float d = (b < 9) ? cur[a * 9 + b] : 0.f;
            dDp[tid] = pack2(d, d);
            __threadfence();
        }
    }
}

// ---------------------------------------------------------------------------
// Main: two samples per thread (one f32x2 stream), D from the constant bank.
// 128-thread blocks: 13 CTAs/SM at 38 regs -> 52/64 warps occupancy ceiling.
// ---------------------------------------------------------------------------
__global__ void __launch_bounds__(128) qnn_main(const float4* __restrict__ x4,
                                                float2* __restrict__ out, int npairs) {
    const int idx = blockIdx.x * blockDim.x + threadIdx.x;
    if (idx >= npairs) return;

    const float4 xa = x4[2 * idx];
    const float4 xb = x4[2 * idx + 1];

    float c0a, s0a, c1a, s1a, c2a, s2a, c3a, s3a;
    float c0b, s0b, c1b, s1b, c2b, s2b, c3b, s3b;
    __sincosf(xa.x, &s0a, &c0a);  __sincosf(xa.y, &s1a, &c1a);
    __sincosf(xa.z, &s2a, &c2a);  __sincosf(xa.w, &s3a, &c3a);
    __sincosf(xb.x, &s0b, &c0b);  __sincosf(xb.y, &s1b, &c1b);
    __sincosf(xb.z, &s2b, &c2b);  __sincosf(xb.w, &s3b, &c3b);

    const unsigned long long pc0 = pack2(c0a, c0b), ps0 = pack2(s0a, s0b);
    const unsigned long long pc1 = pack2(c1a, c1b), ps1 = pack2(s1a, s1b);
    const unsigned long long pc2 = pack2(c2a, c2b), ps2 = pack2(s2a, s2b);
    const unsigned long long pc3 = pack2(c3a, c3b), ps3 = pack2(s3a, s3b);

    // v[0]=1 implicit; v[1..8] = {c3, s3, c2, c2c3, c2s3, s2, s2c3, s2s3}
    unsigned long long pv[9];
    pv[1] = pc3;             pv[2] = ps3;
    pv[3] = pc2;             pv[4] = mul2(pc2, pc3);
    pv[5] = mul2(pc2, ps3);  pv[6] = ps2;
    pv[7] = mul2(ps2, pc3);  pv[8] = mul2(ps2, ps3);
    // u[0]=1 implicit; u[1..8] = {c1, s1, c0, c0c1, c0s1, s0, s0c1, s0s1}
    unsigned long long pu[9];
    pu[1] = pc1;             pu[2] = ps1;
    pu[3] = pc0;             pu[4] = mul2(pc0, pc1);
    pu[5] = mul2(pc0, ps1);  pu[6] = ps0;
    pu[7] = mul2(ps0, pc1);  pu[8] = mul2(ps0, ps1);

    unsigned long long acc = 0;
#pragma unroll
    for (int a = 0; a < 9; ++a) {
        const ulonglong2* row = reinterpret_cast<const ulonglong2*>(cDp + a * 10);
        const ulonglong2 r0 = row[0], r1 = row[1], r2 = row[2], r3 = row[3];
        const unsigned long long d8 = cDp[a * 10 + 8];
        unsigned long long dot = r0.x;                 // * v[0] == 1
        dot = fma2(r0.y, pv[1], dot);
        dot = fma2(r1.x, pv[2], dot);
        dot = fma2(r1.y, pv[3], dot);
        dot = fma2(r2.x, pv[4], dot);
        dot = fma2(r2.y, pv[5], dot);
        dot = fma2(r3.x, pv[6], dot);
        dot = fma2(r3.y, pv[7], dot);
        dot = fma2(d8,   pv[8], dot);
        if (a == 0) acc = dot;                          // * u[0] == 1
        else        acc = fma2(pu[a], dot, acc);
    }

    float lo, hi;
    asm("mov.b64 {%0, %1}, %2;" : "=f"(lo), "=f"(hi) : "l"(acc));
    out[idx] = make_float2(lo, hi);
}

extern "C" void kernel_launch(void* const* d_in, const int* in_sizes, int n_in,
                              void* d_out, int out_size) {
    const float* x = (const float*)d_in[0];
    const float* w = (const float*)d_in[1];
    float2* out = (float2*)d_out;
    const int B = out_size;
    const int npairs = B >> 1;

    void* dDp = nullptr;
    cudaGetSymbolAddress(&dDp, cDp);

    qnn_prologue<<<1, 128>>>(w, (unsigned long long*)dDp);

    const int blocks = (npairs + 127) / 128;
    qnn_main<<<blocks, 128>>>((const float4*)x, out, npairs);
}